// round 2
// baseline (speedup 1.0000x reference)
#include <cuda_runtime.h>
#include <math.h>
#include <stdint.h>

// ---------------- problem constants ----------------
constexpr int D      = 4096;
constexpr int NTOT   = 2000;
constexpr int NL     = 500;
constexpr int NU     = 1500;
constexpr int WAY    = 100;
constexpr int NUW    = NU * WAY;      // 150000
constexpr int WAYD   = WAY * D;       // 409600
constexpr float LAMB  = 10.0f;
constexpr float ALPHAC = 0.2f;

// ---------------- device scratch ----------------
__device__ float g_X1[NTOT * D];
__device__ float g_Z[NTOT * D];
__device__ float g_zn2[NTOT];
__device__ float g_meanL[D], g_meanU[D];
__device__ float g_Sl[WAYD];
__device__ float g_mus[WAYD];
__device__ float g_mn2[WAY];
__device__ float g_Cpart[8 * NUW];
__device__ float g_Kmat[NUW];
__device__ float g_Kpart[600];
__device__ float g_Ksum;
__device__ float g_Pu[NUW];
__device__ float g_colP[WAY];
__device__ float g_Epart[4 * WAYD];
__device__ float g_errPart[16];
__device__ float g_colsumPart[15 * 128];
__device__ int   g_barCount;
__device__ unsigned g_barGen;
__device__ int   g_accN;

// ---------------- helpers ----------------
__device__ __forceinline__ float blockReduceSum(float v) {
    static __shared__ float sh[32];
    __syncthreads();
    int lane = threadIdx.x & 31, wid = threadIdx.x >> 5;
    #pragma unroll
    for (int off = 16; off; off >>= 1) v += __shfl_xor_sync(0xffffffffu, v, off);
    if (lane == 0) sh[wid] = v;
    __syncthreads();
    int nw = (blockDim.x + 31) >> 5;
    float r = 0.0f;
    if (wid == 0) {
        r = (lane < nw) ? sh[lane] : 0.0f;
        #pragma unroll
        for (int off = 16; off; off >>= 1) r += __shfl_xor_sync(0xffffffffu, r, off);
        if (lane == 0) sh[0] = r;
    }
    __syncthreads();
    return sh[0];
}

// ---------------- preprocessing ----------------
__global__ void k_pre1(const float* __restrict__ X) {
    int row = blockIdx.x, t = threadIdx.x;
    __shared__ float buf[D];
    float ss = 0.0f;
    for (int d = t; d < D; d += blockDim.x) {
        float v = sqrtf(X[(size_t)row * D + d] + 1e-6f);
        buf[d] = v; ss += v * v;
    }
    ss = blockReduceSum(ss);
    float inv = 1.0f / fmaxf(sqrtf(ss), 1e-12f);
    for (int d = t; d < D; d += blockDim.x) g_X1[(size_t)row * D + d] = buf[d] * inv;
}

__global__ void k_colmeans() {
    int d = blockIdx.x * blockDim.x + threadIdx.x;
    if (d >= D) return;
    float sL = 0.0f, sU = 0.0f;
    for (int i = 0; i < NL; i++)   sL += g_X1[(size_t)i * D + d];
    for (int i = NL; i < NTOT; i++) sU += g_X1[(size_t)i * D + d];
    g_meanL[d] = sL * (1.0f / NL);
    g_meanU[d] = sU * (1.0f / NU);
}

__global__ void k_pre2() {
    int row = blockIdx.x, t = threadIdx.x;
    __shared__ float buf[D];
    const float* mean = (row < NL) ? g_meanL : g_meanU;
    float ss = 0.0f;
    for (int d = t; d < D; d += blockDim.x) {
        float v = g_X1[(size_t)row * D + d] - mean[d];
        buf[d] = v; ss += v * v;
    }
    ss = blockReduceSum(ss);
    float inv = 1.0f / fmaxf(sqrtf(ss), 1e-12f);
    if (t == 0) g_zn2[row] = ss * inv * inv;
    for (int d = t; d < D; d += blockDim.x) g_Z[(size_t)row * D + d] = buf[d] * inv;
}

__global__ void k_Sl() {
    int idx = blockIdx.x * blockDim.x + threadIdx.x;
    if (idx >= WAYD) return;
    int c = idx >> 12, d = idx & (D - 1);
    float s = 0.0f;
    #pragma unroll
    for (int k = 0; k < 5; k++) s += g_Z[(size_t)(k * WAY + c) * D + d];
    g_Sl[idx] = s;
    g_mus[idx] = s * 0.2f;
}

// ---------------- per-iteration kernels ----------------
__global__ void k_mn2() {
    int j = blockIdx.x;
    float ss = 0.0f;
    for (int d = threadIdx.x; d < D; d += blockDim.x) {
        float v = g_mus[(size_t)j * D + d]; ss += v * v;
    }
    ss = blockReduceSum(ss);
    if (threadIdx.x == 0) g_mn2[j] = ss;
}

// gram: Cpart[ks][i,j] = sum over 512-k-chunk Zu[i,k]*mus[j,k]
__global__ void __launch_bounds__(256) k_gram() {
    const int r0 = blockIdx.x * 64;
    const int k0 = blockIdx.y * 512;
    const int t  = threadIdx.x;
    const int tx = t & 15, ty = t >> 4;
    __shared__ float As[16][65];
    __shared__ float Bs[16][104];
    float acc[4][7];
    #pragma unroll
    for (int a = 0; a < 4; a++)
        #pragma unroll
        for (int b = 0; b < 7; b++) acc[a][b] = 0.0f;
    const float* Zu = g_Z + (size_t)NL * D;
    const int m  = t >> 2;
    const int kb = (t & 3) * 4;
    for (int kt = 0; kt < 512; kt += 16) {
        // load A tile (64 rows x 16 k), float4 per thread
        float4 av = make_float4(0.f, 0.f, 0.f, 0.f);
        if (r0 + m < NU)
            av = *(const float4*)&Zu[(size_t)(r0 + m) * D + k0 + kt + kb];
        As[kb + 0][m] = av.x; As[kb + 1][m] = av.y;
        As[kb + 2][m] = av.z; As[kb + 3][m] = av.w;
        // load B tile (100 cols x 16 k)
        for (int idx = t; idx < 16 * WAY; idx += 256) {
            int kk = idx / WAY, j = idx - kk * WAY;
            Bs[kk][j] = g_mus[(size_t)j * D + k0 + kt + kk];
        }
        __syncthreads();
        #pragma unroll
        for (int k = 0; k < 16; k++) {
            float af[4], bf[7];
            #pragma unroll
            for (int ri = 0; ri < 4; ri++) af[ri] = As[k][ty + 16 * ri];
            #pragma unroll
            for (int ci = 0; ci < 7; ci++) bf[ci] = Bs[k][tx + 16 * ci];
            #pragma unroll
            for (int ri = 0; ri < 4; ri++)
                #pragma unroll
                for (int ci = 0; ci < 7; ci++) acc[ri][ci] = fmaf(af[ri], bf[ci], acc[ri][ci]);
        }
        __syncthreads();
    }
    float* out = g_Cpart + (size_t)blockIdx.y * NUW;
    #pragma unroll
    for (int ri = 0; ri < 4; ri++) {
        int gr = r0 + ty + 16 * ri;
        if (gr >= NU) continue;
        #pragma unroll
        for (int ci = 0; ci < 7; ci++) {
            int j = tx + 16 * ci;
            if (j < WAY) out[gr * WAY + j] = acc[ri][ci];
        }
    }
}

// K = exp(-lam*dist); block partial sums
__global__ void k_expK() {
    int idx = blockIdx.x * blockDim.x + threadIdx.x;
    float kv = 0.0f;
    if (idx < NUW) {
        int i = idx / WAY, j = idx - i * WAY;
        float c = 0.0f;
        #pragma unroll
        for (int s = 0; s < 8; s++) c += g_Cpart[s * NUW + idx];
        float d2 = g_zn2[NL + i] + g_mn2[j] - 2.0f * c;
        float dist = sqrtf(fmaxf(d2, 1e-12f));
        kv = expf(-LAMB * dist);
        g_Kmat[idx] = kv;
    }
    float bs = blockReduceSum(kv);
    if (threadIdx.x == 0) g_Kpart[blockIdx.x] = bs;
}

__global__ void k_ksum(int nparts) {
    float s = 0.0f;
    for (int i = threadIdx.x; i < nparts; i += blockDim.x) s += g_Kpart[i];
    s = blockReduceSum(s);
    if (threadIdx.x == 0) g_Ksum = s;
}

// ---------------- persistent sinkhorn (15 blocks x 512) ----------------
__device__ __forceinline__ void gridbar() {
    __threadfence();
    __syncthreads();
    if (threadIdx.x == 0) {
        volatile unsigned* vg = &g_barGen;
        unsigned gen = *vg;
        if (atomicAdd(&g_barCount, 1) == (int)gridDim.x - 1) {
            *((volatile int*)&g_barCount) = 0;
            __threadfence();
            *vg = gen + 1;
        } else {
            while (*vg == gen) { }
        }
        __threadfence();
    }
    __syncthreads();
}

__global__ void __launch_bounds__(512, 1) k_sinkhorn() {
    const int t = threadIdx.x, w = t >> 5, lane = t & 31;
    const int blk = blockIdx.x;
    const int rbase = blk * 100;
    __shared__ float sWerr[16];
    __shared__ float scolW[16][128];
    const float invKs = 1.0f / g_Ksum;
    float Kr[7][4], a[7], prev[7], b[4], rowsum[7];
    bool rv[7], cv[4];
    int cols[4];
    #pragma unroll
    for (int c = 0; c < 4; c++) {
        int j = lane + 32 * c;
        cols[c] = j; cv[c] = (j < WAY); b[c] = cv[c] ? 1.0f : 0.0f;
    }
    #pragma unroll
    for (int k = 0; k < 7; k++) {
        int r = w + 16 * k;
        rv[k] = (r < 100); a[k] = 1.0f; prev[k] = 0.0f; rowsum[k] = 1.0f;
        #pragma unroll
        for (int c = 0; c < 4; c++)
            Kr[k][c] = (rv[k] && cv[c]) ? g_Kmat[(rbase + r) * WAY + cols[c]] * invKs : 0.0f;
    }

    for (int it = 0; it < 1000; ++it) {
        // Phase A: rowsum + local err
        float werr = 0.0f;
        #pragma unroll
        for (int k = 0; k < 7; k++) {
            float s = 0.0f;
            #pragma unroll
            for (int c = 0; c < 4; c++) s = fmaf(Kr[k][c], b[c], s);
            #pragma unroll
            for (int off = 16; off; off >>= 1) s += __shfl_xor_sync(0xffffffffu, s, off);
            rowsum[k] = a[k] * s;
            if (rv[k]) werr = fmaxf(werr, fabsf(prev[k] - rowsum[k]));
        }
        if (lane == 0) sWerr[w] = werr;
        __syncthreads();
        if (t == 0) {
            float e = sWerr[0];
            #pragma unroll
            for (int ww = 1; ww < 16; ww++) e = fmaxf(e, sWerr[ww]);
            __stcg(&g_errPart[blk], e);
        }
        gridbar();
        // Phase B: global err, done check, row update, colsum partial
        float err = __ldcg(&g_errPart[0]);
        for (int bb = 1; bb < 15; bb++) err = fmaxf(err, __ldcg(&g_errPart[bb]));
        if (err <= 1e-6f) break;
        #pragma unroll
        for (int k = 0; k < 7; k++) {
            if (rv[k]) { a[k] = a[k] / rowsum[k]; prev[k] = rowsum[k]; }
        }
        #pragma unroll
        for (int c = 0; c < 4; c++) {
            float s = 0.0f;
            #pragma unroll
            for (int k = 0; k < 7; k++) s = fmaf(Kr[k][c], a[k], s);
            scolW[w][cols[c]] = cv[c] ? s : 0.0f;
        }
        __syncthreads();
        if (t < 128) {
            float s = scolW[0][t];
            #pragma unroll
            for (int ww = 1; ww < 16; ww++) s += scolW[ww][t];
            __stcg(&g_colsumPart[blk * 128 + t], s);
        }
        gridbar();
        // Phase C: b update (b_new = c / (K^T a_new) -- b factor cancels)
        #pragma unroll
        for (int c = 0; c < 4; c++) {
            if (cv[c]) {
                float cs = __ldcg(&g_colsumPart[cols[c]]);
                for (int bb = 1; bb < 15; bb++) cs += __ldcg(&g_colsumPart[bb * 128 + cols[c]]);
                b[c] = 15.0f / cs;
            }
        }
    }
    // write Pu = a * K * b
    #pragma unroll
    for (int k = 0; k < 7; k++) {
        if (!rv[k]) continue;
        int r = rbase + w + 16 * k;
        #pragma unroll
        for (int c = 0; c < 4; c++)
            if (cv[c]) g_Pu[r * WAY + cols[c]] = a[k] * Kr[k][c] * b[c];
    }
}

// column sums of Pu (deterministic)
__global__ void k_colP() {
    int j = blockIdx.x;
    float s = 0.0f;
    for (int i = threadIdx.x; i < NU; i += blockDim.x) s += g_Pu[i * WAY + j];
    s = blockReduceSum(s);
    if (threadIdx.x == 0) g_colP[j] = s;
}

// Epart[us][j,d] = sum over u-chunk Pu[i,j]*Zu[i,d]
__global__ void __launch_bounds__(256) k_epi() {
    const int d0 = blockIdx.x * 64;
    const int u0 = blockIdx.y * 375;
    const int t  = threadIdx.x;
    const int tx = t & 15, ty = t >> 4;
    __shared__ float Ps[16][104];
    __shared__ float Zs[16][65];
    float acc[7][4];
    #pragma unroll
    for (int a = 0; a < 7; a++)
        #pragma unroll
        for (int b = 0; b < 4; b++) acc[a][b] = 0.0f;
    const float* Zu = g_Z + (size_t)NL * D;
    const int zk = t >> 4;           // 0..15 row within tile
    const int zd = (t & 15) * 4;     // dim group
    for (int kt = 0; kt < 375; kt += 16) {
        for (int idx = t; idx < 16 * WAY; idx += 256) {
            int kk = idx / WAY, j = idx - kk * WAY;
            Ps[kk][j] = (kt + kk < 375) ? g_Pu[(u0 + kt + kk) * WAY + j] : 0.0f;
        }
        float4 zv = make_float4(0.f, 0.f, 0.f, 0.f);
        if (kt + zk < 375)
            zv = *(const float4*)&Zu[(size_t)(u0 + kt + zk) * D + d0 + zd];
        Zs[zk][zd + 0] = zv.x; Zs[zk][zd + 1] = zv.y;
        Zs[zk][zd + 2] = zv.z; Zs[zk][zd + 3] = zv.w;
        __syncthreads();
        #pragma unroll
        for (int k = 0; k < 16; k++) {
            float pf[7], zf[4];
            #pragma unroll
            for (int cj = 0; cj < 7; cj++) pf[cj] = Ps[k][tx + 16 * cj];
            #pragma unroll
            for (int rd = 0; rd < 4; rd++) zf[rd] = Zs[k][ty + 16 * rd];
            #pragma unroll
            for (int cj = 0; cj < 7; cj++)
                #pragma unroll
                for (int rd = 0; rd < 4; rd++) acc[cj][rd] = fmaf(pf[cj], zf[rd], acc[cj][rd]);
        }
        __syncthreads();
    }
    float* out = g_Epart + (size_t)blockIdx.y * WAYD;
    #pragma unroll
    for (int cj = 0; cj < 7; cj++) {
        int j = tx + 16 * cj;
        if (j >= WAY) continue;
        #pragma unroll
        for (int rd = 0; rd < 4; rd++)
            out[(size_t)j * D + d0 + ty + 16 * rd] = acc[cj][rd];
    }
}

__global__ void k_update() {
    int idx = blockIdx.x * blockDim.x + threadIdx.x;
    if (idx >= WAYD) return;
    int j = idx >> 12;
    float E = 0.0f;
    #pragma unroll
    for (int s = 0; s < 4; s++) E += g_Epart[s * WAYD + idx];
    float denom = 5.0f + g_colP[j];
    float emus = (g_Sl[idx] + E) / denom;
    float m = g_mus[idx];
    g_mus[idx] = m + ALPHAC * (emus - m);
}

// ---------------- output ----------------
__global__ void k_out(float* __restrict__ out) {
    int idx = blockIdx.x * blockDim.x + threadIdx.x;
    if (idx == 0) g_accN = 0;
    if (idx < NUW) out[idx] = logf(g_Pu[idx] + 1e-5f);
}

__global__ void k_acc(const int* __restrict__ labels) {
    int i = blockIdx.x * blockDim.x + threadIdx.x;
    if (i >= NU) return;
    const float* row = g_Pu + i * WAY;
    float best = row[0]; int bj = 0;
    for (int j = 1; j < WAY; j++) {
        float v = row[j];
        if (v > best) { best = v; bj = j; }
    }
    if (bj == labels[NL + i]) atomicAdd(&g_accN, 1);
}

__global__ void k_accw(float* __restrict__ out) {
    out[NUW] = (float)g_accN * (1.0f / NU);
}

// ---------------- launch ----------------
extern "C" void kernel_launch(void* const* d_in, const int* in_sizes, int n_in,
                              void* d_out, int out_size) {
    const float* X = (const float*)d_in[0];
    const int* labels = (const int*)d_in[1];
    float* out = (float*)d_out;

    k_pre1<<<NTOT, 256>>>(X);
    k_colmeans<<<D / 256, 256>>>();
    k_pre2<<<NTOT, 256>>>();
    k_Sl<<<WAYD / 256, 256>>>();

    for (int e = 0; e < 21; e++) {
        k_mn2<<<WAY, 256>>>();
        k_gram<<<dim3(24, 8), 256>>>();
        k_expK<<<(NUW + 255) / 256, 256>>>();
        k_ksum<<<1, 512>>>((NUW + 255) / 256);
        k_sinkhorn<<<15, 512>>>();
        if (e < 20) {
            k_colP<<<WAY, 128>>>();
            k_epi<<<dim3(64, 4), 256>>>();
            k_update<<<WAYD / 256, 256>>>();
        }
    }
    k_out<<<(NUW + 255) / 256, 256>>>(out);
    k_acc<<<(NU + 255) / 256, 256>>>(labels);
    if (out_size > NUW) k_accw<<<1, 1>>>(out);
}

// round 3
// speedup vs baseline: 1.7791x; 1.7791x over previous
#include <cuda_runtime.h>
#include <math.h>
#include <stdint.h>

// ---------------- problem constants ----------------
constexpr int D      = 4096;
constexpr int NTOT   = 2000;
constexpr int NL     = 500;
constexpr int NU     = 1500;
constexpr int WAY    = 100;
constexpr int NUW    = NU * WAY;      // 150000
constexpr int WAYD   = WAY * D;       // 409600
constexpr float LAMB  = 10.0f;
constexpr float ALPHAC = 0.2f;

// ---------------- device scratch ----------------
__device__ float g_X1[NTOT * D];
__device__ float g_Z[NTOT * D];
__device__ float g_zn2[NTOT];
__device__ float g_meanL[D], g_meanU[D];
__device__ float g_Sl[WAYD];
__device__ float g_mus[WAYD];
__device__ float g_mn2[WAY];
__device__ float g_Cpart[8 * NUW];
__device__ float g_Kmat[NUW];
__device__ float g_Kpart[600];
__device__ float g_Ksum;
__device__ float g_Pu[NUW];
__device__ float g_colP[WAY];
__device__ float g_Epart[4 * WAYD];
__device__ float g_errPart[16];
__device__ float g_colsumPart[15 * 128];
__device__ int   g_barCount;
__device__ unsigned g_barGen;
__device__ int   g_accN;

// ---------------- helpers ----------------
__device__ __forceinline__ float blockReduceSum(float v) {
    static __shared__ float sh[32];
    __syncthreads();
    int lane = threadIdx.x & 31, wid = threadIdx.x >> 5;
    #pragma unroll
    for (int off = 16; off; off >>= 1) v += __shfl_xor_sync(0xffffffffu, v, off);
    if (lane == 0) sh[wid] = v;
    __syncthreads();
    int nw = (blockDim.x + 31) >> 5;
    float r = 0.0f;
    if (wid == 0) {
        r = (lane < nw) ? sh[lane] : 0.0f;
        #pragma unroll
        for (int off = 16; off; off >>= 1) r += __shfl_xor_sync(0xffffffffu, r, off);
        if (lane == 0) sh[0] = r;
    }
    __syncthreads();
    return sh[0];
}

__device__ __forceinline__ uint32_t f2tf32(float f) {
    uint32_t r;
    asm("cvt.rna.tf32.f32 %0, %1;" : "=r"(r) : "f"(f));
    return r;
}

__device__ __forceinline__ void mma_tf32(float c[4], uint32_t a0, uint32_t a1,
                                         uint32_t a2, uint32_t a3,
                                         uint32_t b0, uint32_t b1) {
    asm volatile(
        "mma.sync.aligned.m16n8k8.row.col.f32.tf32.tf32.f32 "
        "{%0,%1,%2,%3}, {%4,%5,%6,%7}, {%8,%9}, {%0,%1,%2,%3};\n"
        : "+f"(c[0]), "+f"(c[1]), "+f"(c[2]), "+f"(c[3])
        : "r"(a0), "r"(a1), "r"(a2), "r"(a3), "r"(b0), "r"(b1));
}

// ---------------- preprocessing ----------------
__global__ void k_pre1(const float* __restrict__ X) {
    int row = blockIdx.x, t = threadIdx.x;
    __shared__ float buf[D];
    float ss = 0.0f;
    for (int d = t; d < D; d += blockDim.x) {
        float v = sqrtf(X[(size_t)row * D + d] + 1e-6f);
        buf[d] = v; ss += v * v;
    }
    ss = blockReduceSum(ss);
    float inv = 1.0f / fmaxf(sqrtf(ss), 1e-12f);
    for (int d = t; d < D; d += blockDim.x) g_X1[(size_t)row * D + d] = buf[d] * inv;
}

__global__ void k_colmeans() {
    int lane = threadIdx.x & 63;
    int part = threadIdx.x >> 6;         // 0..3
    int d = blockIdx.x * 64 + lane;
    __shared__ float sh[4][64];
    float sL = 0.0f;
    for (int i = part * 125; i < (part + 1) * 125; i++) sL += g_X1[(size_t)i * D + d];
    sh[part][lane] = sL;
    __syncthreads();
    if (part == 0)
        g_meanL[d] = (sh[0][lane] + sh[1][lane] + sh[2][lane] + sh[3][lane]) * (1.0f / NL);
    __syncthreads();
    float sU = 0.0f;
    for (int i = NL + part * 375; i < NL + (part + 1) * 375; i++) sU += g_X1[(size_t)i * D + d];
    sh[part][lane] = sU;
    __syncthreads();
    if (part == 0)
        g_meanU[d] = (sh[0][lane] + sh[1][lane] + sh[2][lane] + sh[3][lane]) * (1.0f / NU);
}

__global__ void k_pre2() {
    int row = blockIdx.x, t = threadIdx.x;
    __shared__ float buf[D];
    const float* mean = (row < NL) ? g_meanL : g_meanU;
    float ss = 0.0f;
    for (int d = t; d < D; d += blockDim.x) {
        float v = g_X1[(size_t)row * D + d] - mean[d];
        buf[d] = v; ss += v * v;
    }
    ss = blockReduceSum(ss);
    float inv = 1.0f / fmaxf(sqrtf(ss), 1e-12f);
    if (t == 0) g_zn2[row] = ss * inv * inv;
    for (int d = t; d < D; d += blockDim.x) g_Z[(size_t)row * D + d] = buf[d] * inv;
}

__global__ void k_Sl() {
    int idx = blockIdx.x * blockDim.x + threadIdx.x;
    if (idx >= WAYD) return;
    int c = idx >> 12, d = idx & (D - 1);
    float s = 0.0f;
    #pragma unroll
    for (int k = 0; k < 5; k++) s += g_Z[(size_t)(k * WAY + c) * D + d];
    g_Sl[idx] = s;
    g_mus[idx] = s * 0.2f;
}

// ---------------- per-iteration kernels ----------------
__global__ void k_mn2() {
    int j = blockIdx.x;
    float ss = 0.0f;
    for (int d = threadIdx.x; d < D; d += blockDim.x) {
        float v = g_mus[(size_t)j * D + d]; ss += v * v;
    }
    ss = blockReduceSum(ss);
    if (threadIdx.x == 0) g_mn2[j] = ss;
}

// ===== tensor-core gram: Cpart[ks][i,j] = sum over 512-k-chunk Zu[i,k]*mus[j,k]
// grid (24 m-blocks, 8 k-splits), 256 threads (8 warps)
// block tile M=64, N=112 (pad of 100), warps 4x2 -> warp tile m16 x n56
__global__ void __launch_bounds__(256) k_gram() {
    const int r0 = blockIdx.x * 64;
    const int k0 = blockIdx.y * 512;
    const int t  = threadIdx.x;
    const int w  = t >> 5, lane = t & 31;
    const int gid = lane >> 2, tig = lane & 3;
    const int mw = w >> 1;            // 0..3
    const int nw = w & 1;             // 0..1
    const int m0w = mw * 16;
    const int n0w = nw * 56;

    __shared__ uint32_t As[64][33];   // [m][k] tf32 bits
    __shared__ uint32_t Bs[112][33];  // [n][k]

    float c[7][4];
    #pragma unroll
    for (int i = 0; i < 7; i++)
        #pragma unroll
        for (int jj = 0; jj < 4; jj++) c[i][jj] = 0.0f;

    const float* Zu = g_Z + (size_t)NL * D;
    const int lr = t >> 3;            // 0..31
    const int lc = (t & 7) * 4;       // k group

    for (int kt = 0; kt < 512; kt += 32) {
        const int kbase = k0 + kt;
        // A: 64 rows x 32 k
        #pragma unroll
        for (int p = 0; p < 2; p++) {
            int r = lr + 32 * p;
            float4 v = make_float4(0.f, 0.f, 0.f, 0.f);
            if (r0 + r < NU) v = *(const float4*)&Zu[(size_t)(r0 + r) * D + kbase + lc];
            As[r][lc + 0] = f2tf32(v.x); As[r][lc + 1] = f2tf32(v.y);
            As[r][lc + 2] = f2tf32(v.z); As[r][lc + 3] = f2tf32(v.w);
        }
        // B: 112 rows x 32 k
        #pragma unroll
        for (int p = 0; p < 4; p++) {
            int r = lr + 32 * p;
            if (r < 112) {
                float4 v = make_float4(0.f, 0.f, 0.f, 0.f);
                if (r < WAY) v = *(const float4*)&g_mus[(size_t)r * D + kbase + lc];
                Bs[r][lc + 0] = f2tf32(v.x); Bs[r][lc + 1] = f2tf32(v.y);
                Bs[r][lc + 2] = f2tf32(v.z); Bs[r][lc + 3] = f2tf32(v.w);
            }
        }
        __syncthreads();
        #pragma unroll
        for (int ks = 0; ks < 4; ks++) {
            const int kk = ks * 8;
            uint32_t a0 = As[m0w + gid][kk + tig];
            uint32_t a1 = As[m0w + gid + 8][kk + tig];
            uint32_t a2 = As[m0w + gid][kk + tig + 4];
            uint32_t a3 = As[m0w + gid + 8][kk + tig + 4];
            #pragma unroll
            for (int nt = 0; nt < 7; nt++) {
                uint32_t b0 = Bs[n0w + nt * 8 + gid][kk + tig];
                uint32_t b1 = Bs[n0w + nt * 8 + gid][kk + tig + 4];
                mma_tf32(c[nt], a0, a1, a2, a3, b0, b1);
            }
        }
        __syncthreads();
    }
    float* out = g_Cpart + (size_t)blockIdx.y * NUW;
    #pragma unroll
    for (int nt = 0; nt < 7; nt++) {
        int j0 = n0w + nt * 8 + tig * 2;
        int gr0 = r0 + m0w + gid;
        #pragma unroll
        for (int h = 0; h < 2; h++) {
            int gr = gr0 + 8 * h;
            if (gr < NU) {
                if (j0 < WAY)     out[gr * WAY + j0]     = c[nt][2 * h];
                if (j0 + 1 < WAY) out[gr * WAY + j0 + 1] = c[nt][2 * h + 1];
            }
        }
    }
}

// K = exp(-lam*dist); block partial sums
__global__ void k_expK() {
    int idx = blockIdx.x * blockDim.x + threadIdx.x;
    float kv = 0.0f;
    if (idx < NUW) {
        int i = idx / WAY, j = idx - i * WAY;
        float c = 0.0f;
        #pragma unroll
        for (int s = 0; s < 8; s++) c += g_Cpart[s * NUW + idx];
        float d2 = g_zn2[NL + i] + g_mn2[j] - 2.0f * c;
        float dist = sqrtf(fmaxf(d2, 1e-12f));
        kv = expf(-LAMB * dist);
        g_Kmat[idx] = kv;
    }
    float bs = blockReduceSum(kv);
    if (threadIdx.x == 0) g_Kpart[blockIdx.x] = bs;
}

__global__ void k_ksum(int nparts) {
    float s = 0.0f;
    for (int i = threadIdx.x; i < nparts; i += blockDim.x) s += g_Kpart[i];
    s = blockReduceSum(s);
    if (threadIdx.x == 0) g_Ksum = s;
}

// ---------------- persistent sinkhorn (15 blocks x 512) ----------------
__device__ __forceinline__ void gridbar() {
    __threadfence();
    __syncthreads();
    if (threadIdx.x == 0) {
        volatile unsigned* vg = &g_barGen;
        unsigned gen = *vg;
        if (atomicAdd(&g_barCount, 1) == (int)gridDim.x - 1) {
            *((volatile int*)&g_barCount) = 0;
            __threadfence();
            *vg = gen + 1;
        } else {
            while (*vg == gen) { }
        }
        __threadfence();
    }
    __syncthreads();
}

__global__ void __launch_bounds__(512, 1) k_sinkhorn() {
    const int t = threadIdx.x, w = t >> 5, lane = t & 31;
    const int blk = blockIdx.x;
    const int rbase = blk * 100;
    __shared__ float sWerr[16];
    __shared__ float scolW[16][128];
    const float invKs = 1.0f / g_Ksum;
    float Kr[7][4], a[7], prev[7], b[4], rowsum[7];
    bool rv[7], cv[4];
    int cols[4];
    #pragma unroll
    for (int c = 0; c < 4; c++) {
        int j = lane + 32 * c;
        cols[c] = j; cv[c] = (j < WAY); b[c] = cv[c] ? 1.0f : 0.0f;
    }
    #pragma unroll
    for (int k = 0; k < 7; k++) {
        int r = w + 16 * k;
        rv[k] = (r < 100); a[k] = 1.0f; prev[k] = 0.0f; rowsum[k] = 1.0f;
        #pragma unroll
        for (int c = 0; c < 4; c++)
            Kr[k][c] = (rv[k] && cv[c]) ? g_Kmat[(rbase + r) * WAY + cols[c]] * invKs : 0.0f;
    }

    for (int it = 0; it < 1000; ++it) {
        float werr = 0.0f;
        #pragma unroll
        for (int k = 0; k < 7; k++) {
            float s = 0.0f;
            #pragma unroll
            for (int c = 0; c < 4; c++) s = fmaf(Kr[k][c], b[c], s);
            #pragma unroll
            for (int off = 16; off; off >>= 1) s += __shfl_xor_sync(0xffffffffu, s, off);
            rowsum[k] = a[k] * s;
            if (rv[k]) werr = fmaxf(werr, fabsf(prev[k] - rowsum[k]));
        }
        if (lane == 0) sWerr[w] = werr;
        __syncthreads();
        if (t == 0) {
            float e = sWerr[0];
            #pragma unroll
            for (int ww = 1; ww < 16; ww++) e = fmaxf(e, sWerr[ww]);
            __stcg(&g_errPart[blk], e);
        }
        gridbar();
        float err = __ldcg(&g_errPart[0]);
        for (int bb = 1; bb < 15; bb++) err = fmaxf(err, __ldcg(&g_errPart[bb]));
        if (err <= 1e-6f) break;
        #pragma unroll
        for (int k = 0; k < 7; k++) {
            if (rv[k]) { a[k] = a[k] / rowsum[k]; prev[k] = rowsum[k]; }
        }
        #pragma unroll
        for (int c = 0; c < 4; c++) {
            float s = 0.0f;
            #pragma unroll
            for (int k = 0; k < 7; k++) s = fmaf(Kr[k][c], a[k], s);
            scolW[w][cols[c]] = cv[c] ? s : 0.0f;
        }
        __syncthreads();
        if (t < 128) {
            float s = scolW[0][t];
            #pragma unroll
            for (int ww = 1; ww < 16; ww++) s += scolW[ww][t];
            __stcg(&g_colsumPart[blk * 128 + t], s);
        }
        gridbar();
        #pragma unroll
        for (int c = 0; c < 4; c++) {
            if (cv[c]) {
                float cs = __ldcg(&g_colsumPart[cols[c]]);
                for (int bb = 1; bb < 15; bb++) cs += __ldcg(&g_colsumPart[bb * 128 + cols[c]]);
                b[c] = 15.0f / cs;
            }
        }
    }
    #pragma unroll
    for (int k = 0; k < 7; k++) {
        if (!rv[k]) continue;
        int r = rbase + w + 16 * k;
        #pragma unroll
        for (int c = 0; c < 4; c++)
            if (cv[c]) g_Pu[r * WAY + cols[c]] = a[k] * Kr[k][c] * b[c];
    }
}

// column sums of Pu (deterministic)
__global__ void k_colP() {
    int j = blockIdx.x;
    float s = 0.0f;
    for (int i = threadIdx.x; i < NU; i += blockDim.x) s += g_Pu[i * WAY + j];
    s = blockReduceSum(s);
    if (threadIdx.x == 0) g_colP[j] = s;
}

// ===== tensor-core epilogue GEMM: Epart[us][j,d] = sum_u Pu[u,j]*Zu[u,d]
// grid (64 n-blocks, 4 u-splits), 256 threads (8 warps)
// block tile M=128 (pad of 100 classes), N=64, K=375 (padded to 384)
__global__ void __launch_bounds__(256) k_epi() {
    const int n0 = blockIdx.x * 64;
    const int u0 = blockIdx.y * 375;
    const int t  = threadIdx.x;
    const int w  = t >> 5, lane = t & 31;
    const int gid = lane >> 2, tig = lane & 3;
    const int m0w = w * 16;

    __shared__ uint32_t As[16][132];  // [k][m] tf32 (Pu^T)
    __shared__ uint32_t Bs[16][68];   // [k][n] tf32 (Zu)

    float c[8][4];
    #pragma unroll
    for (int i = 0; i < 8; i++)
        #pragma unroll
        for (int jj = 0; jj < 4; jj++) c[i][jj] = 0.0f;

    const float* Zu = g_Z + (size_t)NL * D;

    for (int kt = 0; kt < 24; kt++) {
        // A: Pu rows (u) 16 x 128 classes
        #pragma unroll
        for (int p = 0; p < 8; p++) {
            int idx = t + 256 * p;
            int k = idx >> 7, m = idx & 127;
            int kg = kt * 16 + k;
            float v = (m < WAY && kg < 375) ? g_Pu[(u0 + kg) * WAY + m] : 0.0f;
            As[k][m] = f2tf32(v);
        }
        // B: Zu 16 x 64 dims
        {
            int k = t >> 4, nn = (t & 15) * 4;
            int kg = kt * 16 + k;
            float4 v = make_float4(0.f, 0.f, 0.f, 0.f);
            if (kg < 375) v = *(const float4*)&Zu[(size_t)(u0 + kg) * D + n0 + nn];
            Bs[k][nn + 0] = f2tf32(v.x); Bs[k][nn + 1] = f2tf32(v.y);
            Bs[k][nn + 2] = f2tf32(v.z); Bs[k][nn + 3] = f2tf32(v.w);
        }
        __syncthreads();
        #pragma unroll
        for (int ks = 0; ks < 2; ks++) {
            const int kk = ks * 8;
            uint32_t a0 = As[kk + tig][m0w + gid];
            uint32_t a1 = As[kk + tig][m0w + gid + 8];
            uint32_t a2 = As[kk + tig + 4][m0w + gid];
            uint32_t a3 = As[kk + tig + 4][m0w + gid + 8];
            #pragma unroll
            for (int nt = 0; nt < 8; nt++) {
                uint32_t b0 = Bs[kk + tig][nt * 8 + gid];
                uint32_t b1 = Bs[kk + tig + 4][nt * 8 + gid];
                mma_tf32(c[nt], a0, a1, a2, a3, b0, b1);
            }
        }
        __syncthreads();
    }
    float* out = g_Epart + (size_t)blockIdx.y * WAYD;
    #pragma unroll
    for (int nt = 0; nt < 8; nt++) {
        int dcol = n0 + nt * 8 + tig * 2;
        #pragma unroll
        for (int h = 0; h < 2; h++) {
            int j = m0w + gid + 8 * h;
            if (j < WAY) {
                out[(size_t)j * D + dcol]     = c[nt][2 * h];
                out[(size_t)j * D + dcol + 1] = c[nt][2 * h + 1];
            }
        }
    }
}

__global__ void k_update() {
    int idx = blockIdx.x * blockDim.x + threadIdx.x;
    if (idx >= WAYD) return;
    int j = idx >> 12;
    float E = 0.0f;
    #pragma unroll
    for (int s = 0; s < 4; s++) E += g_Epart[s * WAYD + idx];
    float denom = 5.0f + g_colP[j];
    float emus = (g_Sl[idx] + E) / denom;
    float m = g_mus[idx];
    g_mus[idx] = m + ALPHAC * (emus - m);
}

// ---------------- output ----------------
__global__ void k_out(float* __restrict__ out) {
    int idx = blockIdx.x * blockDim.x + threadIdx.x;
    if (idx == 0) g_accN = 0;
    if (idx < NUW) out[idx] = logf(g_Pu[idx] + 1e-5f);
}

__global__ void k_acc(const int* __restrict__ labels) {
    int i = blockIdx.x * blockDim.x + threadIdx.x;
    if (i >= NU) return;
    const float* row = g_Pu + i * WAY;
    float best = row[0]; int bj = 0;
    for (int j = 1; j < WAY; j++) {
        float v = row[j];
        if (v > best) { best = v; bj = j; }
    }
    if (bj == labels[NL + i]) atomicAdd(&g_accN, 1);
}

__global__ void k_accw(float* __restrict__ out) {
    out[NUW] = (float)g_accN * (1.0f / NU);
}

// ---------------- launch ----------------
extern "C" void kernel_launch(void* const* d_in, const int* in_sizes, int n_in,
                              void* d_out, int out_size) {
    const float* X = (const float*)d_in[0];
    const int* labels = (const int*)d_in[1];
    float* out = (float*)d_out;

    k_pre1<<<NTOT, 256>>>(X);
    k_colmeans<<<D / 64, 256>>>();
    k_pre2<<<NTOT, 256>>>();
    k_Sl<<<WAYD / 256, 256>>>();

    for (int e = 0; e < 21; e++) {
        k_mn2<<<WAY, 256>>>();
        k_gram<<<dim3(24, 8), 256>>>();
        k_expK<<<(NUW + 255) / 256, 256>>>();
        k_ksum<<<1, 512>>>((NUW + 255) / 256);
        k_sinkhorn<<<15, 512>>>();
        if (e < 20) {
            k_colP<<<WAY, 128>>>();
            k_epi<<<dim3(64, 4), 256>>>();
            k_update<<<WAYD / 256, 256>>>();
        }
    }
    k_out<<<(NUW + 255) / 256, 256>>>(out);
    k_acc<<<(NU + 255) / 256, 256>>>(labels);
    if (out_size > NUW) k_accw<<<1, 1>>>(out);
}